// round 10
// baseline (speedup 1.0000x reference)
#include <cuda_runtime.h>
#include <cuda_bf16.h>
#include <math.h>
#include <float.h>
#include <stdint.h>

#define N      8192
#define C0     64
#define KSEL   16
#define TCR    16              // per-half-thread candidates (16+16=32 per row)
#define MT     64
#define NT     64
#define NTILE  (N / NT)        // 128
#define KEXT   136             // fp32 rescore rows
#define KB16   144             // bf16 MMA K (128 emb + 16 encoded xyz/norm slots)
#define CSTR   68              // C smem stride (floats)
#define COFF   (MT * CSTR)     // C parity offset (floats)
#define BROWB  304             // bf16 smem row stride bytes (19x16B, odd -> LDSM conflict-free)

// ---------------- scratch ----------------
__device__ __align__(128) float g_f[4][N][C0];            // projected features
__device__ __align__(128) float g_ge[4][N][KEXT];         // fp32 extended rows (exact rescore)
__device__ __align__(128) __nv_bfloat16 g_gb[4][N][KB16]; // bf16 MMA rows (emb + split xyz)
__device__ int g_cand[2][N][32];

__device__ __forceinline__ float leaky(float x) { return fmaxf(x, 0.1f * x); }

__device__ __forceinline__ uint32_t smem_u32(const void* p) {
    uint32_t a;
    asm("{ .reg .u64 t; cvta.to.shared.u64 t, %1; cvt.u32.u64 %0, t; }" : "=r"(a) : "l"(p));
    return a;
}
__device__ __forceinline__ void cp16(uint32_t dst, const void* src) {
    asm volatile("cp.async.cg.shared.global [%0], [%1], 16;" :: "r"(dst), "l"(src));
}
#define CP_COMMIT() asm volatile("cp.async.commit_group;" ::: "memory")
#define CP_WAIT0()  asm volatile("cp.async.wait_group 0;" ::: "memory")

#define BAR_SYNC(id, cnt)   asm volatile("bar.sync %0, %1;"   :: "r"(id), "r"(cnt) : "memory")
#define BAR_ARRIVE(id, cnt) asm volatile("bar.arrive %0, %1;" :: "r"(id), "r"(cnt) : "memory")

__device__ __forceinline__ void ldsm4(uint32_t* r, uint32_t addr) {
    asm volatile("ldmatrix.sync.aligned.m8n8.x4.shared.b16 {%0,%1,%2,%3}, [%4];"
        : "=r"(r[0]), "=r"(r[1]), "=r"(r[2]), "=r"(r[3]) : "r"(addr));
}

__device__ __forceinline__ void mma_bf16(float* c, uint32_t a0, uint32_t a1,
                                         uint32_t a2, uint32_t a3,
                                         uint32_t b0, uint32_t b1) {
    asm volatile(
        "mma.sync.aligned.m16n8k16.row.col.f32.bf16.bf16.f32 "
        "{%0,%1,%2,%3}, {%4,%5,%6,%7}, {%8,%9}, {%0,%1,%2,%3};"
        : "+f"(c[0]), "+f"(c[1]), "+f"(c[2]), "+f"(c[3])
        : "r"(a0), "r"(a1), "r"(a2), "r"(a3), "r"(b0), "r"(b1));
}

__device__ __forceinline__ void split2(float x, __nv_bfloat16& h, __nv_bfloat16& l) {
    h = __float2bfloat16_rn(x);
    l = __float2bfloat16_rn(x - __bfloat162float(h));
}

// smem bytes: A [64*304], B [2][64*304], C [2][64*68*4]
#define SM_A_B 0
#define SM_B_B (MT * BROWB)                // 19456
#define B_TILE (NT * BROWB)                // 19456
#define SM_C_B (SM_B_B + 2 * B_TILE)       // 58368
#define SM_BYTES (SM_C_B + 2 * COFF * 4)   // 93184

// =====================================================================================
// Kernel P: projections + dist embedding + normalize; emits fp32 + bf16-split rows
// =====================================================================================
__global__ __launch_bounds__(256) void kp(
    const float* __restrict__ pc1, const float* __restrict__ pc2,
    const float* __restrict__ feat1, const float* __restrict__ feat2,
    const float* __restrict__ t11w, const float* __restrict__ t11b,
    const float* __restrict__ t22w, const float* __restrict__ t22b,
    const float* __restrict__ dw, const float* __restrict__ db)
{
    extern __shared__ float sm[];
    float* s_tw   = sm;
    float* s_dw   = sm + 4160;
    float* s_feat = sm + 4160 + 8320;
    float* s_f    = sm + 4160 + 8320 + 2112;
    float* s_ss   = s_f + 2080;

    const int combo = blockIdx.y;
    const float* feat = (combo == 0 || combo == 3) ? feat1 : feat2;
    const float* pc   = (combo == 0 || combo == 3) ? pc1   : pc2;
    const float* w    = (combo & 1) ? t22w : t11w;
    const float* b    = (combo & 1) ? t22b : t11b;
    const int side2   = combo & 1;

    const int tid = threadIdx.x;
    const int n0  = blockIdx.x * 32;

    for (int i = tid; i < 4096; i += 256) s_tw[(i >> 6) * 65 + (i & 63)] = w[i];
    for (int i = tid; i < 8192; i += 256) s_dw[(i >> 6) * 65 + (i & 63)] = dw[i];
    for (int i = tid; i < 64 * 32; i += 256) {
        int c = i >> 5, np = i & 31;
        s_feat[c * 33 + np] = feat[c * N + n0 + np];
    }
    if (tid < 32) s_ss[tid] = 0.f;
    __syncthreads();

    for (int it = 0; it < 8; ++it) {
        int i = tid + it * 256;
        int o = i & 63, n = i >> 6;
        float acc = __ldg(b + o);
        #pragma unroll
        for (int c = 0; c < 64; ++c)
            acc = fmaf(s_tw[o * 65 + c], s_feat[c * 33 + n], acc);
        s_f[n * 65 + o] = acc;
        g_f[combo][n0 + n][o] = acc;
    }
    __syncthreads();

    const int n = tid & 31, eg = tid >> 5;
    float gv[16];
    float ss = 0.f;
    #pragma unroll 2
    for (int t = 0; t < 16; ++t) {
        int e = eg * 16 + t;
        float acc = __ldg(db + e);
        #pragma unroll
        for (int c = 0; c < 64; ++c)
            acc = fmaf(s_dw[e * 65 + c], s_f[n * 65 + c], acc);
        gv[t] = acc;
        ss = fmaf(acc, acc, ss);
    }
    atomicAdd(&s_ss[n], ss);
    __syncthreads();
    const float scale = 1.f / (sqrtf(s_ss[n]) + 1e-8f);
    #pragma unroll
    for (int t = 0; t < 16; ++t) {
        float v = gv[t] * scale;
        g_ge[combo][n0 + n][eg * 16 + t] = v;
        g_gb[combo][n0 + n][eg * 16 + t] = __float2bfloat16_rn(v);
    }

    if (tid < 32) {
        int nn = n0 + tid;
        float x0 = pc[0 * N + nn], x1 = pc[1 * N + nn], x2 = pc[2 * N + nn];
        float nrm = x0 * x0 + x1 * x1 + x2 * x2;
        float* row = &g_ge[combo][nn][128];
        __nv_bfloat16* brow = &g_gb[combo][nn][128];
        const __nv_bfloat16 z = __float2bfloat16_rn(0.f);
        __nv_bfloat16 h, l;
        if (side2) {
            row[0] = x0; row[1] = x1; row[2] = x2; row[3] = nrm;
            float xv[3] = {x0, x1, x2};
            #pragma unroll
            for (int c = 0; c < 3; ++c) {
                split2(xv[c], h, l);
                brow[4 * c + 0] = h; brow[4 * c + 1] = h;
                brow[4 * c + 2] = l; brow[4 * c + 3] = l;
            }
            split2(nrm, h, l);
            brow[12] = h; brow[13] = l; brow[14] = z; brow[15] = z;
        } else {
            row[0] = 2.f * x0; row[1] = 2.f * x1; row[2] = 2.f * x2; row[3] = -1.f;
            float xv[3] = {2.f * x0, 2.f * x1, 2.f * x2};
            #pragma unroll
            for (int c = 0; c < 3; ++c) {
                split2(xv[c], h, l);
                brow[4 * c + 0] = h; brow[4 * c + 1] = l;
                brow[4 * c + 2] = h; brow[4 * c + 3] = l;
            }
            const __nv_bfloat16 m1 = __float2bfloat16_rn(-1.f);
            brow[12] = m1; brow[13] = m1; brow[14] = z; brow[15] = z;
        }
        row[4] = 0.f; row[5] = 0.f; row[6] = 0.f; row[7] = 0.f;
    }
}

// =====================================================================================
// Kernel D: warp-specialized. Warps 0-3: MMA+stage+B-prefetch. Warps 4-7: top-k scan.
// Double-buffered C with named-barrier full/free handoff. MT=64, 2 CTAs/SM.
// =====================================================================================
__global__ __launch_bounds__(256, 2) void kd(int dir)
{
    extern __shared__ char smc[];
    const uint32_t sb = smem_u32(smc);
    float* s_c = (float*)(smc + SM_C_B);

    const int tid  = threadIdx.x;
    const int wid  = tid >> 5, lane = tid & 31;
    const int row0 = blockIdx.x * MT;

    const __nv_bfloat16* __restrict__ gA = &g_gb[dir * 2][0][0];
    const __nv_bfloat16* __restrict__ gB = &g_gb[dir * 2 + 1][0][0];

    // ---- initial loads (all threads): A resident + B tile 0 ----
    #pragma unroll
    for (int it = 0; it < 5; ++it) {
        int i = tid + it * 256;
        if (i < 1152) {
            int r = i / 18, q = i % 18;
            cp16(sb + SM_A_B + r * BROWB + q * 16,
                 gA + (size_t)(row0 + r) * KB16 + q * 8);
        }
    }
    #pragma unroll
    for (int it = 0; it < 5; ++it) {
        int i = tid + it * 256;
        if (i < 1152) {
            int r = i / 18, q = i % 18;
            cp16(sb + SM_B_B + r * BROWB + q * 16,
                 gB + (size_t)r * KB16 + q * 8);
        }
    }
    CP_COMMIT();
    CP_WAIT0();
    __syncthreads();

    if (wid < 4) {
        // ================= producers: MMA + stage + B prefetch =================
        const int wr = wid & 1;            // rows wr*32..+31
        const int wc = wid >> 1;           // cols wc*32..+31
        uint32_t a_base[2];
        {
            int r = wr * 32 + (lane & 7) + ((lane >> 3) & 1) * 8;
            a_base[0] = sb + SM_A_B + r * BROWB + (lane >> 4) * 16;
            a_base[1] = a_base[0] + 16 * BROWB;
        }
        uint32_t b_off[2];
        {
            int cI = wc * 32 + (lane & 7) + (lane >> 4) * 8;
            b_off[0] = cI * BROWB + ((lane >> 3) & 1) * 16;
            b_off[1] = b_off[0] + 16 * BROWB;
        }
        const int r0q = lane >> 2;
        const int cq2 = (lane & 3) * 2;

        for (int t = 0; t < NTILE; ++t) {
            const int p = t & 1;
            const uint32_t bbuf = sb + SM_B_B + p * B_TILE;

            if (t + 1 < NTILE) {
                const uint32_t dstb = sb + SM_B_B + ((t + 1) & 1) * B_TILE;
                const __nv_bfloat16* srcb = gB + (size_t)(t + 1) * NT * KB16;
                #pragma unroll
                for (int it = 0; it < 9; ++it) {
                    int i = tid + it * 128;      // tid in 0..127
                    int r = i / 18, q = i % 18;
                    cp16(dstb + r * BROWB + q * 16, srcb + (size_t)r * KB16 + q * 8);
                }
                CP_COMMIT();
            }
            if (t >= 2) BAR_SYNC(3 + p, 256);    // wait C[p] free

            float c[2][4][4];
            #pragma unroll
            for (int rb = 0; rb < 2; ++rb)
                #pragma unroll
                for (int cb = 0; cb < 4; ++cb)
                    #pragma unroll
                    for (int q = 0; q < 4; ++q) c[rb][cb][q] = 0.f;

            #pragma unroll
            for (int kb = 0; kb < 9; ++kb) {
                const uint32_t kadd = kb * 32;
                uint32_t a[2][4], b[2][4];
                ldsm4(a[0], a_base[0] + kadd);
                ldsm4(a[1], a_base[1] + kadd);
                ldsm4(b[0], bbuf + b_off[0] + kadd);
                ldsm4(b[1], bbuf + b_off[1] + kadd);
                #pragma unroll
                for (int rb = 0; rb < 2; ++rb) {
                    mma_bf16(c[rb][0], a[rb][0], a[rb][1], a[rb][2], a[rb][3], b[0][0], b[0][1]);
                    mma_bf16(c[rb][1], a[rb][0], a[rb][1], a[rb][2], a[rb][3], b[0][2], b[0][3]);
                    mma_bf16(c[rb][2], a[rb][0], a[rb][1], a[rb][2], a[rb][3], b[1][0], b[1][1]);
                    mma_bf16(c[rb][3], a[rb][0], a[rb][1], a[rb][2], a[rb][3], b[1][2], b[1][3]);
                }
            }

            // stage C[p]
            float* cp_ = s_c + p * COFF;
            #pragma unroll
            for (int rb = 0; rb < 2; ++rb) {
                const int rr = wr * 32 + rb * 16 + r0q;
                #pragma unroll
                for (int cb = 0; cb < 4; ++cb) {
                    const int cc = wc * 32 + cb * 8 + cq2;
                    cp_[rr * CSTR + cc]           = c[rb][cb][0];
                    cp_[rr * CSTR + cc + 1]       = c[rb][cb][1];
                    cp_[(rr + 8) * CSTR + cc]     = c[rb][cb][2];
                    cp_[(rr + 8) * CSTR + cc + 1] = c[rb][cb][3];
                }
            }
            BAR_SYNC(1 + p, 256);               // announce C[p] full (sync form: mem-ordered)

            CP_WAIT0();
            BAR_SYNC(5, 128);                   // producer-only: B[t+1] landed
        }
    } else {
        // ================= consumers: per-half-row top-16 =================
        float ts[TCR];
        int   ti[TCR];
        #pragma unroll
        for (int q = 0; q < TCR; ++q) { ts[q] = -FLT_MAX; ti[q] = 0; }

        const int et   = tid - 128;
        const int erow = et & 63;
        const int half = et >> 6;

        for (int t = 0; t < NTILE; ++t) {
            const int p = t & 1;
            BAR_SYNC(1 + p, 256);               // wait C[p] full
            const float* crow = s_c + p * COFF + erow * CSTR + half * 32;
            const int jb0 = t * NT + half * 32;
            #pragma unroll 1
            for (int cb = 0; cb < 4; ++cb) {
                float4 v0 = *(const float4*)(crow + cb * 8);
                float4 v1 = *(const float4*)(crow + cb * 8 + 4);
                float acc[8] = {v0.x, v0.y, v0.z, v0.w, v1.x, v1.y, v1.z, v1.w};
                unsigned m = 0;
                #pragma unroll
                for (int jj = 0; jj < 8; ++jj)
                    if (acc[jj] > ts[TCR - 1]) m |= (1u << jj);
                while (__any_sync(0xffffffffu, m != 0)) {
                    if (m) {
                        int jj = __ffs(m) - 1;
                        m &= m - 1;
                        float cs = acc[jj];
                        if (cs > ts[TCR - 1]) {
                            int ci = jb0 + cb * 8 + jj;
                            #pragma unroll
                            for (int q = 0; q < TCR; ++q) {
                                if (cs > ts[q]) {
                                    float tf = ts[q]; ts[q] = cs; cs = tf;
                                    int   tx = ti[q]; ti[q] = ci; ci = tx;
                                }
                            }
                        }
                    }
                }
            }
            BAR_ARRIVE(3 + p, 256);             // C[p] free
        }

        #pragma unroll
        for (int q = 0; q < TCR; ++q)
            g_cand[dir][row0 + erow][half * TCR + q] = ti[q];
    }
}

// =====================================================================================
// Kernel M: exact fp32 rescore of 32 candidates -> top-16 -> gather+MLP+maxpool
// =====================================================================================
__device__ __forceinline__ unsigned long long makeKey(float s, int j)
{
    unsigned u = __float_as_uint(s);
    u = (u & 0x80000000u) ? ~u : (u | 0x80000000u);
    return ((unsigned long long)u << 32) | (unsigned)(~j);
}

__global__ __launch_bounds__(256) void km(
    const float* __restrict__ pc1, const float* __restrict__ pc2,
    const float* __restrict__ posw, const float* __restrict__ posb,
    const float* __restrict__ mw, const float* __restrict__ mb,
    float* __restrict__ out)
{
    __shared__ float s_mw[64 * 65];
    __shared__ float s_g1[8][KEXT];
    __shared__ int   s_sel[8][KSEL];
    __shared__ float s_v[8][65];

    const int tid  = threadIdx.x;
    const int lane = tid & 31;
    const int rg   = tid >> 5;
    const int dir  = blockIdx.y;
    const int row  = blockIdx.x * 8 + rg;

    const float* x1p = dir ? pc2 : pc1;
    const float* x2p = dir ? pc1 : pc2;
    const float* q1  = &g_f[dir * 2][0][0];
    const float* q2  = &g_f[dir * 2 + 1][0][0];
    const float* g1  = &g_ge[dir * 2][0][0];
    const float* g2  = &g_ge[dir * 2 + 1][0][0];

    for (int i = tid; i < 4096; i += 256)
        s_mw[(i >> 6) * 65 + (i & 63)] = mw[i];
    for (int i = tid; i < 8 * KEXT; i += 256)
        s_g1[i / KEXT][i % KEXT] =
            g1[(size_t)(blockIdx.x * 8 + i / KEXT) * KEXT + (i % KEXT)];
    __syncthreads();

    // exact rescore: every lane owns one candidate
    unsigned long long key;
    {
        int j = g_cand[dir][row][lane];
        const float4* g2r = (const float4*)(g2 + (size_t)j * KEXT);
        float s = 0.f;
        #pragma unroll 8
        for (int kqq = 0; kqq < 34; ++kqq) {
            float4 av = *(const float4*)&s_g1[rg][kqq * 4];
            float4 bv = __ldg(g2r + kqq);
            s = fmaf(av.x, bv.x, s); s = fmaf(av.y, bv.y, s);
            s = fmaf(av.z, bv.z, s); s = fmaf(av.w, bv.w, s);
        }
        key = makeKey(s, j);
    }

    #pragma unroll 1
    for (int r = 0; r < KSEL; ++r) {
        unsigned long long mx = key;
        #pragma unroll
        for (int off = 16; off; off >>= 1) {
            unsigned long long o = __shfl_xor_sync(0xffffffffu, mx, off);
            mx = (o > mx) ? o : mx;
        }
        if (lane == 0) s_sel[rg][r] = (int)(~(unsigned)mx);
        if (key == mx) key = 0ULL;
    }
    __syncwarp();

    const float x10 = x1p[row], x11 = x1p[N + row], x12 = x1p[2 * N + row];
    const float q1a = q1[row * 64 + lane];
    const float q1b = q1[row * 64 + lane + 32];
    const float pa0 = __ldg(posw + lane * 3 + 0), pa1 = __ldg(posw + lane * 3 + 1), pa2 = __ldg(posw + lane * 3 + 2);
    const float pb0 = __ldg(posw + (lane + 32) * 3 + 0), pb1 = __ldg(posw + (lane + 32) * 3 + 1), pb2 = __ldg(posw + (lane + 32) * 3 + 2);
    const float ba  = __ldg(posb + lane),      bb  = __ldg(posb + lane + 32);
    const float mba = __ldg(mb + lane),        mbb = __ldg(mb + lane + 32);

    float bestA = -FLT_MAX, bestB = -FLT_MAX;

    #pragma unroll 1
    for (int kk = 0; kk < KSEL; ++kk) {
        int j = s_sel[rg][kk];
        float d0 = x2p[j] - x10, d1 = x2p[N + j] - x11, d2 = x2p[2 * N + j] - x12;
        float posA = fmaf(pa2, d2, fmaf(pa1, d1, fmaf(pa0, d0, ba)));
        float posB = fmaf(pb2, d2, fmaf(pb1, d1, fmaf(pb0, d0, bb)));
        float va = leaky(q2[j * 64 + lane]      + q1a + posA);
        float vb = leaky(q2[j * 64 + lane + 32] + q1b + posB);
        s_v[rg][lane]      = va;
        s_v[rg][lane + 32] = vb;
        __syncwarp();
        float ha = mba, hb = mbb;
        #pragma unroll
        for (int c = 0; c < 64; ++c) {
            float vc = s_v[rg][c];
            ha = fmaf(s_mw[lane * 65 + c],        vc, ha);
            hb = fmaf(s_mw[(lane + 32) * 65 + c], vc, hb);
        }
        bestA = fmaxf(bestA, leaky(ha));
        bestB = fmaxf(bestB, leaky(hb));
        __syncwarp();
    }

    out[dir * (64 * N) + lane * N + row]        = bestA;
    out[dir * (64 * N) + (lane + 32) * N + row] = bestB;
}

// =====================================================================================
extern "C" void kernel_launch(void* const* d_in, const int* in_sizes, int n_in,
                              void* d_out, int out_size)
{
    const float* pc1   = (const float*)d_in[0];
    const float* pc2   = (const float*)d_in[1];
    const float* feat1 = (const float*)d_in[2];
    const float* feat2 = (const float*)d_in[3];
    const float* t11w  = (const float*)d_in[4];
    const float* t11b  = (const float*)d_in[5];
    const float* t22w  = (const float*)d_in[6];
    const float* t22b  = (const float*)d_in[7];
    const float* posw  = (const float*)d_in[8];
    const float* posb  = (const float*)d_in[9];
    const float* dw    = (const float*)d_in[10];
    const float* db    = (const float*)d_in[11];
    const float* mw    = (const float*)d_in[12];
    const float* mb    = (const float*)d_in[13];
    float* out = (float*)d_out;

    const int smP = 66816;
    cudaFuncSetAttribute(kp, cudaFuncAttributeMaxDynamicSharedMemorySize, smP);
    cudaFuncSetAttribute(kd, cudaFuncAttributeMaxDynamicSharedMemorySize, SM_BYTES);

    kp<<<dim3(N / 32, 4), 256, smP>>>(pc1, pc2, feat1, feat2,
                                      t11w, t11b, t22w, t22b, dw, db);
    kd<<<dim3(N / MT), 256, SM_BYTES>>>(0);
    kd<<<dim3(N / MT), 256, SM_BYTES>>>(1);
    km<<<dim3(N / 8, 2), 256>>>(pc1, pc2, posw, posb, mw, mb, out);
}

// round 11
// speedup vs baseline: 1.3207x; 1.3207x over previous
#include <cuda_runtime.h>
#include <cuda_bf16.h>
#include <math.h>
#include <float.h>
#include <stdint.h>

#define N      8192
#define C0     64
#define KSEL   16
#define TCR    16              // per-half-thread candidates (16+16=32 per row)
#define MT     128
#define NT     64
#define NTILE  (N / NT)        // 128
#define KEXT   136             // fp32 rescore rows
#define KB16   144             // bf16 MMA K (128 emb + 16 encoded xyz/norm slots)
#define CSTR   68              // C smem stride (floats)
#define BROWB  304             // bf16 smem row stride bytes (19x16B, odd -> LDSM conflict-free)

// ---------------- scratch ----------------
__device__ __align__(128) float g_f[4][N][C0];            // projected features
__device__ __align__(128) float g_ge[4][N][KEXT];         // fp32 extended rows (exact rescore)
__device__ __align__(128) __nv_bfloat16 g_gb[4][N][KB16]; // bf16 MMA rows (emb + split xyz)
__device__ int g_cand[2][N][32];

__device__ __forceinline__ float leaky(float x) { return fmaxf(x, 0.1f * x); }

__device__ __forceinline__ uint32_t smem_u32(const void* p) {
    uint32_t a;
    asm("{ .reg .u64 t; cvta.to.shared.u64 t, %1; cvt.u32.u64 %0, t; }" : "=r"(a) : "l"(p));
    return a;
}
__device__ __forceinline__ void cp16(uint32_t dst, const void* src) {
    asm volatile("cp.async.cg.shared.global [%0], [%1], 16;" :: "r"(dst), "l"(src));
}
#define CP_COMMIT() asm volatile("cp.async.commit_group;" ::: "memory")
#define CP_WAIT0()  asm volatile("cp.async.wait_group 0;" ::: "memory")

__device__ __forceinline__ void ldsm4(uint32_t* r, uint32_t addr) {
    asm volatile("ldmatrix.sync.aligned.m8n8.x4.shared.b16 {%0,%1,%2,%3}, [%4];"
        : "=r"(r[0]), "=r"(r[1]), "=r"(r[2]), "=r"(r[3]) : "r"(addr));
}

__device__ __forceinline__ void mma_bf16(float* c, uint32_t a0, uint32_t a1,
                                         uint32_t a2, uint32_t a3,
                                         uint32_t b0, uint32_t b1) {
    asm volatile(
        "mma.sync.aligned.m16n8k16.row.col.f32.bf16.bf16.f32 "
        "{%0,%1,%2,%3}, {%4,%5,%6,%7}, {%8,%9}, {%0,%1,%2,%3};"
        : "+f"(c[0]), "+f"(c[1]), "+f"(c[2]), "+f"(c[3])
        : "r"(a0), "r"(a1), "r"(a2), "r"(a3), "r"(b0), "r"(b1));
}

__device__ __forceinline__ void split2(float x, __nv_bfloat16& h, __nv_bfloat16& l) {
    h = __float2bfloat16_rn(x);
    l = __float2bfloat16_rn(x - __bfloat162float(h));
}

// kd smem bytes: A [128*304], B [2][64*304], C [128*68*4]
#define SM_A_B 0
#define SM_B_B (MT * BROWB)                // 38912
#define B_TILE (NT * BROWB)                // 19456
#define SM_C_B (SM_B_B + 2 * B_TILE)       // 77824
#define SM_BYTES (SM_C_B + MT * CSTR * 4)  // 112640

// km smem layout (floats)
#define KM_MW   0                           // [64*65] = 4160
#define KM_G1   4160                        // [8*136] = 1088
#define KM_V    5248                        // [8*16*68] = 8704
#define KM_SEL  13952                       // [8*16] ints = 128
#define KM_FLOATS 14080
#define KM_BYTES  (KM_FLOATS * 4)           // 56320

// =====================================================================================
// Kernel P: projections + dist embedding + normalize; emits fp32 + bf16-split rows
// =====================================================================================
__global__ __launch_bounds__(256) void kp(
    const float* __restrict__ pc1, const float* __restrict__ pc2,
    const float* __restrict__ feat1, const float* __restrict__ feat2,
    const float* __restrict__ t11w, const float* __restrict__ t11b,
    const float* __restrict__ t22w, const float* __restrict__ t22b,
    const float* __restrict__ dw, const float* __restrict__ db)
{
    extern __shared__ float sm[];
    float* s_tw   = sm;
    float* s_dw   = sm + 4160;
    float* s_feat = sm + 4160 + 8320;
    float* s_f    = sm + 4160 + 8320 + 2112;
    float* s_ss   = s_f + 2080;

    const int combo = blockIdx.y;
    const float* feat = (combo == 0 || combo == 3) ? feat1 : feat2;
    const float* pc   = (combo == 0 || combo == 3) ? pc1   : pc2;
    const float* w    = (combo & 1) ? t22w : t11w;
    const float* b    = (combo & 1) ? t22b : t11b;
    const int side2   = combo & 1;

    const int tid = threadIdx.x;
    const int n0  = blockIdx.x * 32;

    for (int i = tid; i < 4096; i += 256) s_tw[(i >> 6) * 65 + (i & 63)] = w[i];
    for (int i = tid; i < 8192; i += 256) s_dw[(i >> 6) * 65 + (i & 63)] = dw[i];
    for (int i = tid; i < 64 * 32; i += 256) {
        int c = i >> 5, np = i & 31;
        s_feat[c * 33 + np] = feat[c * N + n0 + np];
    }
    if (tid < 32) s_ss[tid] = 0.f;
    __syncthreads();

    for (int it = 0; it < 8; ++it) {
        int i = tid + it * 256;
        int o = i & 63, n = i >> 6;
        float acc = __ldg(b + o);
        #pragma unroll
        for (int c = 0; c < 64; ++c)
            acc = fmaf(s_tw[o * 65 + c], s_feat[c * 33 + n], acc);
        s_f[n * 65 + o] = acc;
        g_f[combo][n0 + n][o] = acc;
    }
    __syncthreads();

    const int n = tid & 31, eg = tid >> 5;
    float gv[16];
    float ss = 0.f;
    #pragma unroll 2
    for (int t = 0; t < 16; ++t) {
        int e = eg * 16 + t;
        float acc = __ldg(db + e);
        #pragma unroll
        for (int c = 0; c < 64; ++c)
            acc = fmaf(s_dw[e * 65 + c], s_f[n * 65 + c], acc);
        gv[t] = acc;
        ss = fmaf(acc, acc, ss);
    }
    atomicAdd(&s_ss[n], ss);
    __syncthreads();
    const float scale = 1.f / (sqrtf(s_ss[n]) + 1e-8f);
    #pragma unroll
    for (int t = 0; t < 16; ++t) {
        float v = gv[t] * scale;
        g_ge[combo][n0 + n][eg * 16 + t] = v;
        g_gb[combo][n0 + n][eg * 16 + t] = __float2bfloat16_rn(v);
    }

    if (tid < 32) {
        int nn = n0 + tid;
        float x0 = pc[0 * N + nn], x1 = pc[1 * N + nn], x2 = pc[2 * N + nn];
        float nrm = x0 * x0 + x1 * x1 + x2 * x2;
        float* row = &g_ge[combo][nn][128];
        __nv_bfloat16* brow = &g_gb[combo][nn][128];
        const __nv_bfloat16 z = __float2bfloat16_rn(0.f);
        __nv_bfloat16 h, l;
        if (side2) {
            row[0] = x0; row[1] = x1; row[2] = x2; row[3] = nrm;
            float xv[3] = {x0, x1, x2};
            #pragma unroll
            for (int c = 0; c < 3; ++c) {
                split2(xv[c], h, l);
                brow[4 * c + 0] = h; brow[4 * c + 1] = h;
                brow[4 * c + 2] = l; brow[4 * c + 3] = l;
            }
            split2(nrm, h, l);
            brow[12] = h; brow[13] = l; brow[14] = z; brow[15] = z;
        } else {
            row[0] = 2.f * x0; row[1] = 2.f * x1; row[2] = 2.f * x2; row[3] = -1.f;
            float xv[3] = {2.f * x0, 2.f * x1, 2.f * x2};
            #pragma unroll
            for (int c = 0; c < 3; ++c) {
                split2(xv[c], h, l);
                brow[4 * c + 0] = h; brow[4 * c + 1] = l;
                brow[4 * c + 2] = h; brow[4 * c + 3] = l;
            }
            const __nv_bfloat16 m1 = __float2bfloat16_rn(-1.f);
            brow[12] = m1; brow[13] = m1; brow[14] = z; brow[15] = z;
        }
        row[4] = 0.f; row[5] = 0.f; row[6] = 0.f; row[7] = 0.f;
    }
}

// =====================================================================================
// Kernel D (R8 config): bf16 m16n8k16 full-score GEMM (K=144) + top-16 per half-row.
// 256 threads (8 warps: 4 row-groups x 2 col-groups, warp tile 32x32). 1 CTA/SM.
// =====================================================================================
__global__ __launch_bounds__(256, 1) void kd()
{
    extern __shared__ char smc[];
    const uint32_t sb = smem_u32(smc);
    float* s_c = (float*)(smc + SM_C_B);

    const int tid  = threadIdx.x;
    const int wid  = tid >> 5, lane = tid & 31;
    const int dir  = blockIdx.y;
    const int row0 = blockIdx.x * MT;

    const int wr = wid & 3;
    const int wc = wid >> 2;

    const __nv_bfloat16* __restrict__ gA = &g_gb[dir * 2][0][0];
    const __nv_bfloat16* __restrict__ gB = &g_gb[dir * 2 + 1][0][0];

    // ---- A resident: 128 rows x 18 chunks of 16B ----
    #pragma unroll
    for (int it = 0; it < 9; ++it) {
        int i = tid + it * 256;              // 0..2303
        int r = i / 18, q = i % 18;
        cp16(sb + SM_A_B + r * BROWB + q * 16,
             gA + (size_t)(row0 + r) * KB16 + q * 8);
    }
    // ---- B tile 0: 64 rows x 18 chunks ----
    #pragma unroll
    for (int it = 0; it < 5; ++it) {
        int i = tid + it * 256;
        if (i < 1152) {
            int r = i / 18, q = i % 18;
            cp16(sb + SM_B_B + r * BROWB + q * 16,
                 gB + (size_t)r * KB16 + q * 8);
        }
    }
    CP_COMMIT();
    CP_WAIT0();
    __syncthreads();

    float ts[TCR];
    int   ti[TCR];
    #pragma unroll
    for (int q = 0; q < TCR; ++q) { ts[q] = -FLT_MAX; ti[q] = 0; }

    uint32_t a_base[2];
    {
        int r = wr * 32 + (lane & 7) + ((lane >> 3) & 1) * 8;
        a_base[0] = sb + SM_A_B + r * BROWB + (lane >> 4) * 16;
        a_base[1] = a_base[0] + 16 * BROWB;
    }
    uint32_t b_off[2];
    {
        int cI = wc * 32 + (lane & 7) + (lane >> 4) * 8;
        b_off[0] = cI * BROWB + ((lane >> 3) & 1) * 16;
        b_off[1] = b_off[0] + 16 * BROWB;
    }

    const int r0q = lane >> 2;
    const int cq2 = (lane & 3) * 2;
    const int erow = tid & 127;           // epilogue row
    const int half = tid >> 7;            // 0: cols 0-31, 1: cols 32-63
    const float* crow = s_c + erow * CSTR + half * 32;

    for (int t = 0; t < NTILE; ++t) {
        const uint32_t bbuf = sb + SM_B_B + (t & 1) * B_TILE;

        if (t + 1 < NTILE) {
            const uint32_t dstb = sb + SM_B_B + ((t + 1) & 1) * B_TILE;
            const __nv_bfloat16* srcb = gB + (size_t)(t + 1) * NT * KB16;
            #pragma unroll
            for (int it = 0; it < 5; ++it) {
                int i = tid + it * 256;
                if (i < 1152) {
                    int r = i / 18, q = i % 18;
                    cp16(dstb + r * BROWB + q * 16, srcb + (size_t)r * KB16 + q * 8);
                }
            }
            CP_COMMIT();
        }

        // ---- MMA: warp tile 32x32, K=144 (9 k-steps) ----
        float c[2][4][4];
        #pragma unroll
        for (int rb = 0; rb < 2; ++rb)
            #pragma unroll
            for (int cb = 0; cb < 4; ++cb)
                #pragma unroll
                for (int q = 0; q < 4; ++q) c[rb][cb][q] = 0.f;

        #pragma unroll
        for (int kb = 0; kb < 9; ++kb) {
            const uint32_t kadd = kb * 32;
            uint32_t a[2][4], b[2][4];
            ldsm4(a[0], a_base[0] + kadd);
            ldsm4(a[1], a_base[1] + kadd);
            ldsm4(b[0], bbuf + b_off[0] + kadd);
            ldsm4(b[1], bbuf + b_off[1] + kadd);
            #pragma unroll
            for (int rb = 0; rb < 2; ++rb) {
                mma_bf16(c[rb][0], a[rb][0], a[rb][1], a[rb][2], a[rb][3], b[0][0], b[0][1]);
                mma_bf16(c[rb][1], a[rb][0], a[rb][1], a[rb][2], a[rb][3], b[0][2], b[0][3]);
                mma_bf16(c[rb][2], a[rb][0], a[rb][1], a[rb][2], a[rb][3], b[1][0], b[1][1]);
                mma_bf16(c[rb][3], a[rb][0], a[rb][1], a[rb][2], a[rb][3], b[1][2], b[1][3]);
            }
        }
        __syncthreads();

        // ---- stage C ----
        #pragma unroll
        for (int rb = 0; rb < 2; ++rb) {
            const int rr = wr * 32 + rb * 16 + r0q;
            #pragma unroll
            for (int cb = 0; cb < 4; ++cb) {
                const int cc = wc * 32 + cb * 8 + cq2;
                s_c[rr * CSTR + cc]           = c[rb][cb][0];
                s_c[rr * CSTR + cc + 1]       = c[rb][cb][1];
                s_c[(rr + 8) * CSTR + cc]     = c[rb][cb][2];
                s_c[(rr + 8) * CSTR + cc + 1] = c[rb][cb][3];
            }
        }
        __syncthreads();

        // ---- all threads: half-row streaming top-16 ----
        {
            const int jb0 = t * NT + half * 32;
            #pragma unroll 1
            for (int cb = 0; cb < 4; ++cb) {
                float4 v0 = *(const float4*)(crow + cb * 8);
                float4 v1 = *(const float4*)(crow + cb * 8 + 4);
                float acc[8] = {v0.x, v0.y, v0.z, v0.w, v1.x, v1.y, v1.z, v1.w};
                unsigned m = 0;
                #pragma unroll
                for (int jj = 0; jj < 8; ++jj)
                    if (acc[jj] > ts[TCR - 1]) m |= (1u << jj);
                while (__any_sync(0xffffffffu, m != 0)) {
                    if (m) {
                        int jj = __ffs(m) - 1;
                        m &= m - 1;
                        float cs = acc[jj];
                        if (cs > ts[TCR - 1]) {
                            int ci = jb0 + cb * 8 + jj;
                            #pragma unroll
                            for (int q = 0; q < TCR; ++q) {
                                if (cs > ts[q]) {
                                    float tf = ts[q]; ts[q] = cs; cs = tf;
                                    int   tx = ti[q]; ti[q] = ci; ci = tx;
                                }
                            }
                        }
                    }
                }
            }
        }
        CP_WAIT0();
        __syncthreads();
    }

    #pragma unroll
    for (int q = 0; q < TCR; ++q)
        g_cand[dir][row0 + erow][half * TCR + q] = ti[q];
}

// =====================================================================================
// Kernel M: exact fp32 rescore of 32 candidates -> top-16, then 3-phase epilogue:
// (b) ILP gather+leaky for all 16 selected into s_v, (c) batched MLP (c-outer, k-inner).
// =====================================================================================
__device__ __forceinline__ unsigned long long makeKey(float s, int j)
{
    unsigned u = __float_as_uint(s);
    u = (u & 0x80000000u) ? ~u : (u | 0x80000000u);
    return ((unsigned long long)u << 32) | (unsigned)(~j);
}

__global__ __launch_bounds__(256) void km(
    const float* __restrict__ pc1, const float* __restrict__ pc2,
    const float* __restrict__ posw, const float* __restrict__ posb,
    const float* __restrict__ mw, const float* __restrict__ mb,
    float* __restrict__ out)
{
    extern __shared__ float skm[];
    float* s_mw  = skm + KM_MW;               // [64][65]
    float* s_g1  = skm + KM_G1;               // [8][136]
    float* s_v   = skm + KM_V;                // [8][16][68]
    int*   s_sel = (int*)(skm + KM_SEL);      // [8][16]

    const int tid  = threadIdx.x;
    const int lane = tid & 31;
    const int rg   = tid >> 5;
    const int dir  = blockIdx.y;
    const int row  = blockIdx.x * 8 + rg;

    const float* x1p = dir ? pc2 : pc1;
    const float* x2p = dir ? pc1 : pc2;
    const float* q1  = &g_f[dir * 2][0][0];
    const float* q2  = &g_f[dir * 2 + 1][0][0];
    const float* g1  = &g_ge[dir * 2][0][0];
    const float* g2  = &g_ge[dir * 2 + 1][0][0];

    for (int i = tid; i < 4096; i += 256)
        s_mw[(i >> 6) * 65 + (i & 63)] = mw[i];
    for (int i = tid; i < 8 * KEXT; i += 256)
        s_g1[(i / KEXT) * KEXT + (i % KEXT)] =
            g1[(size_t)(blockIdx.x * 8 + i / KEXT) * KEXT + (i % KEXT)];
    __syncthreads();

    // ---- exact rescore: every lane owns one candidate ----
    unsigned long long key;
    {
        int j = g_cand[dir][row][lane];
        const float4* g2r = (const float4*)(g2 + (size_t)j * KEXT);
        const float* g1r = s_g1 + rg * KEXT;
        float s = 0.f;
        #pragma unroll 8
        for (int kqq = 0; kqq < 34; ++kqq) {
            float4 av = *(const float4*)(g1r + kqq * 4);
            float4 bv = __ldg(g2r + kqq);
            s = fmaf(av.x, bv.x, s); s = fmaf(av.y, bv.y, s);
            s = fmaf(av.z, bv.z, s); s = fmaf(av.w, bv.w, s);
        }
        key = makeKey(s, j);
    }

    #pragma unroll 1
    for (int r = 0; r < KSEL; ++r) {
        unsigned long long mx = key;
        #pragma unroll
        for (int off = 16; off; off >>= 1) {
            unsigned long long o = __shfl_xor_sync(0xffffffffu, mx, off);
            mx = (o > mx) ? o : mx;
        }
        if (lane == 0) s_sel[rg * KSEL + r] = (int)(~(unsigned)mx);
        if (key == mx) key = 0ULL;
    }
    __syncwarp();

    const float x10 = x1p[row], x11 = x1p[N + row], x12 = x1p[2 * N + row];
    const float q1a = q1[row * 64 + lane];
    const float q1b = q1[row * 64 + lane + 32];
    const float pa0 = __ldg(posw + lane * 3 + 0), pa1 = __ldg(posw + lane * 3 + 1), pa2 = __ldg(posw + lane * 3 + 2);
    const float pb0 = __ldg(posw + (lane + 32) * 3 + 0), pb1 = __ldg(posw + (lane + 32) * 3 + 1), pb2 = __ldg(posw + (lane + 32) * 3 + 2);
    const float ba  = __ldg(posb + lane),      bb  = __ldg(posb + lane + 32);
    const float mba = __ldg(mb + lane),        mbb = __ldg(mb + lane + 32);

    // ---- phase (b): gather + fused add+leaky for all 16 selected (ILP) ----
    float* vbase = s_v + rg * (KSEL * 68);
    #pragma unroll 4
    for (int kk = 0; kk < KSEL; ++kk) {
        int j = s_sel[rg * KSEL + kk];
        float d0 = x2p[j] - x10, d1 = x2p[N + j] - x11, d2 = x2p[2 * N + j] - x12;
        float posA = fmaf(pa2, d2, fmaf(pa1, d1, fmaf(pa0, d0, ba)));
        float posB = fmaf(pb2, d2, fmaf(pb1, d1, fmaf(pb0, d0, bb)));
        vbase[kk * 68 + lane]      = leaky(q2[j * 64 + lane]      + q1a + posA);
        vbase[kk * 68 + lane + 32] = leaky(q2[j * 64 + lane + 32] + q1b + posB);
    }
    __syncwarp();

    // ---- phase (c): batched MLP, c-outer / k-inner, 32 independent accumulators ----
    float ha[KSEL], hb[KSEL];
    #pragma unroll
    for (int k = 0; k < KSEL; ++k) { ha[k] = mba; hb[k] = mbb; }

    #pragma unroll 4
    for (int c = 0; c < 64; ++c) {
        float wA = s_mw[lane * 65 + c];
        float wB = s_mw[(lane + 32) * 65 + c];
        #pragma unroll
        for (int k = 0; k < KSEL; ++k) {
            float vc = vbase[k * 68 + c];
            ha[k] = fmaf(wA, vc, ha[k]);
            hb[k] = fmaf(wB, vc, hb[k]);
        }
    }

    float bestA = -FLT_MAX, bestB = -FLT_MAX;
    #pragma unroll
    for (int k = 0; k < KSEL; ++k) {
        bestA = fmaxf(bestA, leaky(ha[k]));
        bestB = fmaxf(bestB, leaky(hb[k]));
    }

    out[dir * (64 * N) + lane * N + row]        = bestA;
    out[dir * (64 * N) + (lane + 32) * N + row] = bestB;
}

// =====================================================================================
extern "C" void kernel_launch(void* const* d_in, const int* in_sizes, int n_in,
                              void* d_out, int out_size)
{
    const float* pc1   = (const float*)d_in[0];
    const float* pc2   = (const float*)d_in[1];
    const float* feat1 = (const float*)d_in[2];
    const float* feat2 = (const float*)d_in[3];
    const float* t11w  = (const float*)d_in[4];
    const float* t11b  = (const float*)d_in[5];
    const float* t22w  = (const float*)d_in[6];
    const float* t22b  = (const float*)d_in[7];
    const float* posw  = (const float*)d_in[8];
    const float* posb  = (const float*)d_in[9];
    const float* dw    = (const float*)d_in[10];
    const float* db    = (const float*)d_in[11];
    const float* mw    = (const float*)d_in[12];
    const float* mb    = (const float*)d_in[13];
    float* out = (float*)d_out;

    const int smP = 66816;
    cudaFuncSetAttribute(kp, cudaFuncAttributeMaxDynamicSharedMemorySize, smP);
    cudaFuncSetAttribute(kd, cudaFuncAttributeMaxDynamicSharedMemorySize, SM_BYTES);
    cudaFuncSetAttribute(km, cudaFuncAttributeMaxDynamicSharedMemorySize, KM_BYTES);

    kp<<<dim3(N / 32, 4), 256, smP>>>(pc1, pc2, feat1, feat2,
                                      t11w, t11b, t22w, t22b, dw, db);
    kd<<<dim3(N / MT, 2), 256, SM_BYTES>>>();
    km<<<dim3(N / 8, 2), 256, KM_BYTES>>>(pc1, pc2, posw, posb, mw, mb, out);
}

// round 13
// speedup vs baseline: 1.4873x; 1.1261x over previous
#include <cuda_runtime.h>
#include <cuda_bf16.h>
#include <math.h>
#include <float.h>
#include <stdint.h>

#define N      8192
#define C0     64
#define KSEL   16
#define TCR    16              // per-half-thread candidates (16+16=32 per row)
#define MT     64
#define NT     64
#define NTILE  (N / NT)        // 128
#define KEXT   136             // fp32 rescore rows
#define KB16   144             // bf16 MMA K (128 emb + 16 encoded xyz/norm slots)
#define CSTR   68              // C smem stride (floats)
#define COFF   (MT * CSTR)     // C parity offset (floats)
#define BROWB  304             // bf16 smem row stride bytes (19x16B, odd -> LDSM conflict-free)

// ---------------- scratch ----------------
__device__ __align__(128) float g_f[4][N][C0];            // projected features
__device__ __align__(128) float g_ge[4][N][KEXT];         // fp32 extended rows (exact rescore)
__device__ __align__(128) __nv_bfloat16 g_gb[4][N][KB16]; // bf16 MMA rows (emb + split xyz)
__device__ int g_cand[2][N][32];

__device__ __forceinline__ float leaky(float x) { return fmaxf(x, 0.1f * x); }

__device__ __forceinline__ uint32_t smem_u32(const void* p) {
    uint32_t a;
    asm("{ .reg .u64 t; cvta.to.shared.u64 t, %1; cvt.u32.u64 %0, t; }" : "=r"(a) : "l"(p));
    return a;
}
__device__ __forceinline__ void cp16(uint32_t dst, const void* src) {
    asm volatile("cp.async.cg.shared.global [%0], [%1], 16;" :: "r"(dst), "l"(src));
}
#define CP_COMMIT() asm volatile("cp.async.commit_group;" ::: "memory")
#define CP_WAIT0()  asm volatile("cp.async.wait_group 0;" ::: "memory")

#define BAR_SYNC(id, cnt)   asm volatile("bar.sync %0, %1;"   :: "r"(id), "r"(cnt) : "memory")
#define BAR_ARRIVE(id, cnt) asm volatile("bar.arrive %0, %1;" :: "r"(id), "r"(cnt) : "memory")

__device__ __forceinline__ void ldsm4(uint32_t* r, uint32_t addr) {
    asm volatile("ldmatrix.sync.aligned.m8n8.x4.shared.b16 {%0,%1,%2,%3}, [%4];"
        : "=r"(r[0]), "=r"(r[1]), "=r"(r[2]), "=r"(r[3]) : "r"(addr));
}

__device__ __forceinline__ void mma_bf16(float* c, uint32_t a0, uint32_t a1,
                                         uint32_t a2, uint32_t a3,
                                         uint32_t b0, uint32_t b1) {
    asm volatile(
        "mma.sync.aligned.m16n8k16.row.col.f32.bf16.bf16.f32 "
        "{%0,%1,%2,%3}, {%4,%5,%6,%7}, {%8,%9}, {%0,%1,%2,%3};"
        : "+f"(c[0]), "+f"(c[1]), "+f"(c[2]), "+f"(c[3])
        : "r"(a0), "r"(a1), "r"(a2), "r"(a3), "r"(b0), "r"(b1));
}

__device__ __forceinline__ void split2(float x, __nv_bfloat16& h, __nv_bfloat16& l) {
    h = __float2bfloat16_rn(x);
    l = __float2bfloat16_rn(x - __bfloat162float(h));
}

// kd smem bytes: A [64*304], B [2][64*304], C [2][64*68*4]
#define SM_A_B 0
#define SM_B_B (MT * BROWB)                // 19456
#define B_TILE (NT * BROWB)                // 19456
#define SM_C_B (SM_B_B + 2 * B_TILE)       // 58368
#define SM_BYTES (SM_C_B + 2 * COFF * 4)   // 93184

// km smem layout (floats)
#define KM_MW   0                           // [64*65] = 4160
#define KM_G1   4160                        // [8*136] = 1088
#define KM_V    5248                        // [8*16*68] = 8704
#define KM_SEL  13952                       // [8*16] ints = 128
#define KM_FLOATS 14080
#define KM_BYTES  (KM_FLOATS * 4)           // 56320

// =====================================================================================
// Kernel P: projections + dist embedding + normalize; emits fp32 + bf16-split rows
// =====================================================================================
__global__ __launch_bounds__(256) void kp(
    const float* __restrict__ pc1, const float* __restrict__ pc2,
    const float* __restrict__ feat1, const float* __restrict__ feat2,
    const float* __restrict__ t11w, const float* __restrict__ t11b,
    const float* __restrict__ t22w, const float* __restrict__ t22b,
    const float* __restrict__ dw, const float* __restrict__ db)
{
    extern __shared__ float sm[];
    float* s_tw   = sm;
    float* s_dw   = sm + 4160;
    float* s_feat = sm + 4160 + 8320;
    float* s_f    = sm + 4160 + 8320 + 2112;
    float* s_ss   = s_f + 2080;

    const int combo = blockIdx.y;
    const float* feat = (combo == 0 || combo == 3) ? feat1 : feat2;
    const float* pc   = (combo == 0 || combo == 3) ? pc1   : pc2;
    const float* w    = (combo & 1) ? t22w : t11w;
    const float* b    = (combo & 1) ? t22b : t11b;
    const int side2   = combo & 1;

    const int tid = threadIdx.x;
    const int n0  = blockIdx.x * 32;

    for (int i = tid; i < 4096; i += 256) s_tw[(i >> 6) * 65 + (i & 63)] = w[i];
    for (int i = tid; i < 8192; i += 256) s_dw[(i >> 6) * 65 + (i & 63)] = dw[i];
    for (int i = tid; i < 64 * 32; i += 256) {
        int c = i >> 5, np = i & 31;
        s_feat[c * 33 + np] = feat[c * N + n0 + np];
    }
    if (tid < 32) s_ss[tid] = 0.f;
    __syncthreads();

    for (int it = 0; it < 8; ++it) {
        int i = tid + it * 256;
        int o = i & 63, n = i >> 6;
        float acc = __ldg(b + o);
        #pragma unroll
        for (int c = 0; c < 64; ++c)
            acc = fmaf(s_tw[o * 65 + c], s_feat[c * 33 + n], acc);
        s_f[n * 65 + o] = acc;
        g_f[combo][n0 + n][o] = acc;
    }
    __syncthreads();

    const int n = tid & 31, eg = tid >> 5;
    float gv[16];
    float ss = 0.f;
    #pragma unroll 2
    for (int t = 0; t < 16; ++t) {
        int e = eg * 16 + t;
        float acc = __ldg(db + e);
        #pragma unroll
        for (int c = 0; c < 64; ++c)
            acc = fmaf(s_dw[e * 65 + c], s_f[n * 65 + c], acc);
        gv[t] = acc;
        ss = fmaf(acc, acc, ss);
    }
    atomicAdd(&s_ss[n], ss);
    __syncthreads();
    const float scale = 1.f / (sqrtf(s_ss[n]) + 1e-8f);
    #pragma unroll
    for (int t = 0; t < 16; ++t) {
        float v = gv[t] * scale;
        g_ge[combo][n0 + n][eg * 16 + t] = v;
        g_gb[combo][n0 + n][eg * 16 + t] = __float2bfloat16_rn(v);
    }

    if (tid < 32) {
        int nn = n0 + tid;
        float x0 = pc[0 * N + nn], x1 = pc[1 * N + nn], x2 = pc[2 * N + nn];
        float nrm = x0 * x0 + x1 * x1 + x2 * x2;
        float* row = &g_ge[combo][nn][128];
        __nv_bfloat16* brow = &g_gb[combo][nn][128];
        const __nv_bfloat16 z = __float2bfloat16_rn(0.f);
        __nv_bfloat16 h, l;
        if (side2) {
            row[0] = x0; row[1] = x1; row[2] = x2; row[3] = nrm;
            float xv[3] = {x0, x1, x2};
            #pragma unroll
            for (int c = 0; c < 3; ++c) {
                split2(xv[c], h, l);
                brow[4 * c + 0] = h; brow[4 * c + 1] = h;
                brow[4 * c + 2] = l; brow[4 * c + 3] = l;
            }
            split2(nrm, h, l);
            brow[12] = h; brow[13] = l; brow[14] = z; brow[15] = z;
        } else {
            row[0] = 2.f * x0; row[1] = 2.f * x1; row[2] = 2.f * x2; row[3] = -1.f;
            float xv[3] = {2.f * x0, 2.f * x1, 2.f * x2};
            #pragma unroll
            for (int c = 0; c < 3; ++c) {
                split2(xv[c], h, l);
                brow[4 * c + 0] = h; brow[4 * c + 1] = l;
                brow[4 * c + 2] = h; brow[4 * c + 3] = l;
            }
            const __nv_bfloat16 m1 = __float2bfloat16_rn(-1.f);
            brow[12] = m1; brow[13] = m1; brow[14] = z; brow[15] = z;
        }
        row[4] = 0.f; row[5] = 0.f; row[6] = 0.f; row[7] = 0.f;
    }
}

// =====================================================================================
// Kernel D: warp-specialized, SINGLE launch (dir = blockIdx.y). MT=64, 2 CTAs/SM.
// Warps 0-3: MMA+stage+B-prefetch. Warps 4-7: top-k scan. Double-buffered C handoff.
// =====================================================================================
__global__ __launch_bounds__(256, 2) void kd()
{
    extern __shared__ char smc[];
    const uint32_t sb = smem_u32(smc);
    float* s_c = (float*)(smc + SM_C_B);

    const int tid  = threadIdx.x;
    const int wid  = tid >> 5, lane = tid & 31;
    const int dir  = blockIdx.y;
    const int row0 = blockIdx.x * MT;

    const __nv_bfloat16* __restrict__ gA = &g_gb[dir * 2][0][0];
    const __nv_bfloat16* __restrict__ gB = &g_gb[dir * 2 + 1][0][0];

    // ---- initial loads (all threads): A resident + B tile 0 ----
    #pragma unroll
    for (int it = 0; it < 5; ++it) {
        int i = tid + it * 256;
        if (i < 1152) {
            int r = i / 18, q = i % 18;
            cp16(sb + SM_A_B + r * BROWB + q * 16,
                 gA + (size_t)(row0 + r) * KB16 + q * 8);
        }
    }
    #pragma unroll
    for (int it = 0; it < 5; ++it) {
        int i = tid + it * 256;
        if (i < 1152) {
            int r = i / 18, q = i % 18;
            cp16(sb + SM_B_B + r * BROWB + q * 16,
                 gB + (size_t)r * KB16 + q * 8);
        }
    }
    CP_COMMIT();
    CP_WAIT0();
    __syncthreads();

    if (wid < 4) {
        // ================= producers: MMA + stage + B prefetch =================
        const int wr = wid & 1;            // rows wr*32..+31
        const int wc = wid >> 1;           // cols wc*32..+31
        uint32_t a_base[2];
        {
            int r = wr * 32 + (lane & 7) + ((lane >> 3) & 1) * 8;
            a_base[0] = sb + SM_A_B + r * BROWB + (lane >> 4) * 16;
            a_base[1] = a_base[0] + 16 * BROWB;
        }
        uint32_t b_off[2];
        {
            int cI = wc * 32 + (lane & 7) + (lane >> 4) * 8;
            b_off[0] = cI * BROWB + ((lane >> 3) & 1) * 16;
            b_off[1] = b_off[0] + 16 * BROWB;
        }
        const int r0q = lane >> 2;
        const int cq2 = (lane & 3) * 2;

        for (int t = 0; t < NTILE; ++t) {
            const int p = t & 1;
            const uint32_t bbuf = sb + SM_B_B + p * B_TILE;

            if (t + 1 < NTILE) {
                const uint32_t dstb = sb + SM_B_B + ((t + 1) & 1) * B_TILE;
                const __nv_bfloat16* srcb = gB + (size_t)(t + 1) * NT * KB16;
                #pragma unroll
                for (int it = 0; it < 9; ++it) {
                    int i = tid + it * 128;      // tid in 0..127
                    int r = i / 18, q = i % 18;
                    cp16(dstb + r * BROWB + q * 16, srcb + (size_t)r * KB16 + q * 8);
                }
                CP_COMMIT();
            }
            if (t >= 2) BAR_SYNC(3 + p, 256);    // wait C[p] free

            float c[2][4][4];
            #pragma unroll
            for (int rb = 0; rb < 2; ++rb)
                #pragma unroll
                for (int cb = 0; cb < 4; ++cb)
                    #pragma unroll
                    for (int q = 0; q < 4; ++q) c[rb][cb][q] = 0.f;

            #pragma unroll
            for (int kb = 0; kb < 9; ++kb) {
                const uint32_t kadd = kb * 32;
                uint32_t a[2][4], b[2][4];
                ldsm4(a[0], a_base[0] + kadd);
                ldsm4(a[1], a_base[1] + kadd);
                ldsm4(b[0], bbuf + b_off[0] + kadd);
                ldsm4(b[1], bbuf + b_off[1] + kadd);
                #pragma unroll
                for (int rb = 0; rb < 2; ++rb) {
                    mma_bf16(c[rb][0], a[rb][0], a[rb][1], a[rb][2], a[rb][3], b[0][0], b[0][1]);
                    mma_bf16(c[rb][1], a[rb][0], a[rb][1], a[rb][2], a[rb][3], b[0][2], b[0][3]);
                    mma_bf16(c[rb][2], a[rb][0], a[rb][1], a[rb][2], a[rb][3], b[1][0], b[1][1]);
                    mma_bf16(c[rb][3], a[rb][0], a[rb][1], a[rb][2], a[rb][3], b[1][2], b[1][3]);
                }
            }

            // stage C[p]
            float* cp_ = s_c + p * COFF;
            #pragma unroll
            for (int rb = 0; rb < 2; ++rb) {
                const int rr = wr * 32 + rb * 16 + r0q;
                #pragma unroll
                for (int cb = 0; cb < 4; ++cb) {
                    const int cc = wc * 32 + cb * 8 + cq2;
                    cp_[rr * CSTR + cc]           = c[rb][cb][0];
                    cp_[rr * CSTR + cc + 1]       = c[rb][cb][1];
                    cp_[(rr + 8) * CSTR + cc]     = c[rb][cb][2];
                    cp_[(rr + 8) * CSTR + cc + 1] = c[rb][cb][3];
                }
            }
            BAR_SYNC(1 + p, 256);               // announce C[p] full

            CP_WAIT0();
            BAR_SYNC(5, 128);                   // producer-only: B[t+1] landed
        }
    } else {
        // ================= consumers: per-half-row top-16 =================
        float ts[TCR];
        int   ti[TCR];
        #pragma unroll
        for (int q = 0; q < TCR; ++q) { ts[q] = -FLT_MAX; ti[q] = 0; }

        const int et   = tid - 128;
        const int erow = et & 63;
        const int half = et >> 6;

        for (int t = 0; t < NTILE; ++t) {
            const int p = t & 1;
            BAR_SYNC(1 + p, 256);               // wait C[p] full
            const float* crow = s_c + p * COFF + erow * CSTR + half * 32;
            const int jb0 = t * NT + half * 32;
            #pragma unroll 1
            for (int cb = 0; cb < 4; ++cb) {
                float4 v0 = *(const float4*)(crow + cb * 8);
                float4 v1 = *(const float4*)(crow + cb * 8 + 4);
                float acc[8] = {v0.x, v0.y, v0.z, v0.w, v1.x, v1.y, v1.z, v1.w};
                unsigned m = 0;
                #pragma unroll
                for (int jj = 0; jj < 8; ++jj)
                    if (acc[jj] > ts[TCR - 1]) m |= (1u << jj);
                while (__any_sync(0xffffffffu, m != 0)) {
                    if (m) {
                        int jj = __ffs(m) - 1;
                        m &= m - 1;
                        float cs = acc[jj];
                        if (cs > ts[TCR - 1]) {
                            int ci = jb0 + cb * 8 + jj;
                            #pragma unroll
                            for (int q = 0; q < TCR; ++q) {
                                if (cs > ts[q]) {
                                    float tf = ts[q]; ts[q] = cs; cs = tf;
                                    int   tx = ti[q]; ti[q] = ci; ci = tx;
                                }
                            }
                        }
                    }
                }
            }
            BAR_ARRIVE(3 + p, 256);             // C[p] free
        }

        #pragma unroll
        for (int q = 0; q < TCR; ++q)
            g_cand[dir][row0 + erow][half * TCR + q] = ti[q];
    }
}

// =====================================================================================
// Kernel M: exact fp32 rescore of 32 candidates -> top-16, then 3-phase epilogue
// =====================================================================================
__device__ __forceinline__ unsigned long long makeKey(float s, int j)
{
    unsigned u = __float_as_uint(s);
    u = (u & 0x80000000u) ? ~u : (u | 0x80000000u);
    return ((unsigned long long)u << 32) | (unsigned)(~j);
}

__global__ __launch_bounds__(256) void km(
    const float* __restrict__ pc1, const float* __restrict__ pc2,
    const float* __restrict__ posw, const float* __restrict__ posb,
    const float* __restrict__ mw, const float* __restrict__ mb,
    float* __restrict__ out)
{
    extern __shared__ float skm[];
    float* s_mw  = skm + KM_MW;               // [64][65]
    float* s_g1  = skm + KM_G1;               // [8][136]
    float* s_v   = skm + KM_V;                // [8][16][68]
    int*   s_sel = (int*)(skm + KM_SEL);      // [8][16]

    const int tid  = threadIdx.x;
    const int lane = tid & 31;
    const int rg   = tid >> 5;
    const int dir  = blockIdx.y;
    const int row  = blockIdx.x * 8 + rg;

    const float* x1p = dir ? pc2 : pc1;
    const float* x2p = dir ? pc1 : pc2;
    const float* q1  = &g_f[dir * 2][0][0];
    const float* q2  = &g_f[dir * 2 + 1][0][0];
    const float* g1  = &g_ge[dir * 2][0][0];
    const float* g2  = &g_ge[dir * 2 + 1][0][0];

    for (int i = tid; i < 4096; i += 256)
        s_mw[(i >> 6) * 65 + (i & 63)] = mw[i];
    for (int i = tid; i < 8 * KEXT; i += 256)
        s_g1[(i / KEXT) * KEXT + (i % KEXT)] =
            g1[(size_t)(blockIdx.x * 8 + i / KEXT) * KEXT + (i % KEXT)];
    __syncthreads();

    // ---- exact rescore: every lane owns one candidate ----
    unsigned long long key;
    {
        int j = g_cand[dir][row][lane];
        const float4* g2r = (const float4*)(g2 + (size_t)j * KEXT);
        const float* g1r = s_g1 + rg * KEXT;
        float s = 0.f;
        #pragma unroll 8
        for (int kqq = 0; kqq < 34; ++kqq) {
            float4 av = *(const float4*)(g1r + kqq * 4);
            float4 bv = __ldg(g2r + kqq);
            s = fmaf(av.x, bv.x, s); s = fmaf(av.y, bv.y, s);
            s = fmaf(av.z, bv.z, s); s = fmaf(av.w, bv.w, s);
        }
        key = makeKey(s, j);
    }

    #pragma unroll 1
    for (int r = 0; r < KSEL; ++r) {
        unsigned long long mx = key;
        #pragma unroll
        for (int off = 16; off; off >>= 1) {
            unsigned long long o = __shfl_xor_sync(0xffffffffu, mx, off);
            mx = (o > mx) ? o : mx;
        }
        if (lane == 0) s_sel[rg * KSEL + r] = (int)(~(unsigned)mx);
        if (key == mx) key = 0ULL;
    }
    __syncwarp();

    const float x10 = x1p[row], x11 = x1p[N + row], x12 = x1p[2 * N + row];
    const float q1a = q1[row * 64 + lane];
    const float q1b = q1[row * 64 + lane + 32];
    const float pa0 = __ldg(posw + lane * 3 + 0), pa1 = __ldg(posw + lane * 3 + 1), pa2 = __ldg(posw + lane * 3 + 2);
    const float pb0 = __ldg(posw + (lane + 32) * 3 + 0), pb1 = __ldg(posw + (lane + 32) * 3 + 1), pb2 = __ldg(posw + (lane + 32) * 3 + 2);
    const float ba  = __ldg(posb + lane),      bb  = __ldg(posb + lane + 32);
    const float mba = __ldg(mb + lane),        mbb = __ldg(mb + lane + 32);

    // ---- phase (b): gather + fused add+leaky for all 16 selected (ILP) ----
    float* vbase = s_v + rg * (KSEL * 68);
    #pragma unroll 4
    for (int kk = 0; kk < KSEL; ++kk) {
        int j = s_sel[rg * KSEL + kk];
        float d0 = x2p[j] - x10, d1 = x2p[N + j] - x11, d2 = x2p[2 * N + j] - x12;
        float posA = fmaf(pa2, d2, fmaf(pa1, d1, fmaf(pa0, d0, ba)));
        float posB = fmaf(pb2, d2, fmaf(pb1, d1, fmaf(pb0, d0, bb)));
        vbase[kk * 68 + lane]      = leaky(q2[j * 64 + lane]      + q1a + posA);
        vbase[kk * 68 + lane + 32] = leaky(q2[j * 64 + lane + 32] + q1b + posB);
    }
    __syncwarp();

    // ---- phase (c): batched MLP, c-outer / k-inner, 32 independent accumulators ----
    float ha[KSEL], hb[KSEL];
    #pragma unroll
    for (int k = 0; k < KSEL; ++k) { ha[k] = mba; hb[k] = mbb; }

    #pragma unroll 4
    for (int c = 0; c < 64; ++c) {
        float wA = s_mw[lane * 65 + c];
        float wB = s_mw[(lane + 32) * 65 + c];
        #pragma unroll
        for (int k = 0; k < KSEL; ++k) {
            float vc = vbase[k * 68 + c];
            ha[k] = fmaf(wA, vc, ha[k]);
            hb[k] = fmaf(wB, vc, hb[k]);
        }
    }

    float bestA = -FLT_MAX, bestB = -FLT_MAX;
    #pragma unroll
    for (int k = 0; k < KSEL; ++k) {
        bestA = fmaxf(bestA, leaky(ha[k]));
        bestB = fmaxf(bestB, leaky(hb[k]));
    }

    out[dir * (64 * N) + lane * N + row]        = bestA;
    out[dir * (64 * N) + (lane + 32) * N + row] = bestB;
}

// =====================================================================================
extern "C" void kernel_launch(void* const* d_in, const int* in_sizes, int n_in,
                              void* d_out, int out_size)
{
    const float* pc1   = (const float*)d_in[0];
    const float* pc2   = (const float*)d_in[1];
    const float* feat1 = (const float*)d_in[2];
    const float* feat2 = (const float*)d_in[3];
    const float* t11w  = (const float*)d_in[4];
    const float* t11b  = (const float*)d_in[5];
    const float* t22w  = (const float*)d_in[6];
    const float* t22b  = (const float*)d_in[7];
    const float* posw  = (const float*)d_in[8];
    const float* posb  = (const float*)d_in[9];
    const float* dw    = (const float*)d_in[10];
    const float* db    = (const float*)d_in[11];
    const float* mw    = (const float*)d_in[12];
    const float* mb    = (const float*)d_in[13];
    float* out = (float*)d_out;

    const int smP = 66816;
    cudaFuncSetAttribute(kp, cudaFuncAttributeMaxDynamicSharedMemorySize, smP);
    cudaFuncSetAttribute(kd, cudaFuncAttributeMaxDynamicSharedMemorySize, SM_BYTES);
    cudaFuncSetAttribute(km, cudaFuncAttributeMaxDynamicSharedMemorySize, KM_BYTES);

    kp<<<dim3(N / 32, 4), 256, smP>>>(pc1, pc2, feat1, feat2,
                                      t11w, t11b, t22w, t22b, dw, db);
    kd<<<dim3(N / MT, 2), 256, SM_BYTES>>>();
    km<<<dim3(N / 8, 2), 256, KM_BYTES>>>(pc1, pc2, posw, posb, mw, mb, out);
}